// round 12
// baseline (speedup 1.0000x reference)
#include <cuda_runtime.h>
#include <cstdint>

// NAF layer: A = -0.5 * d^T (L L^T) d  ==  -0.5 * ||L^T d||^2
// L lower-triangular, packed row-major (tril order): (i,j) at i*(i+1)/2 + j.
// Diagonal entries exp(x)+eps, off-diagonal raw.
//
// R11: chunked waits were neutral (82.5% DRAM) -> latency already hidden
// cross-warp; residual is per-row warp churn + wave tail. This version is a
// PERSISTENT grid-stride kernel: each warp owns two 2080-float smem buffers
// and loops over ~18 rows, prefetching row r+stride into buf^1 (one cp.async
// commit group) while consuming row r from buf. wait_group 1 -> the consumed
// group was committed a full row-period (~4000 cyc) earlier: zero exposed
// latency, continuous per-warp streaming, single wave.
// One warp per batch row; lane l owns columns j=l and j=l+32.

#define NB_ACTIONS 64
#define NB_ELEMS   2080            // 520 float4 per row
#define NB_F4      520
#define EPSV       1e-7f
#define TRI(i) ((i) * ((i) + 1) / 2)
#define WPB        2               // warps per block
#define NBLOCKS    912             // 152 SMs * 6 blocks/SM (ok if 148 SMs)

__global__ __launch_bounds__(32 * WPB, 6)
void naf_kernel(const float* __restrict__ Lf,
                const float* __restrict__ mu,
                const float* __restrict__ a,
                float* __restrict__ out,
                int B)
{
    __shared__ float sbuf[WPB][2][NB_ELEMS];   // 33,280 B/block (static)

    const int lane  = threadIdx.x & 31;
    const int wl    = threadIdx.x >> 5;
    const int gwarp = blockIdx.x * WPB + wl;
    const int strd  = gridDim.x * WPB;
    const int j1    = lane + 32;

    unsigned int sbase0 = (unsigned int)__cvta_generic_to_shared(sbuf[wl][0]);
    unsigned int sbase1 = (unsigned int)__cvta_generic_to_shared(sbuf[wl][1]);

    // ---- Prologue: prefetch first row into buf 0 ----
    int row = gwarp;
    if (row < B) {
        const float4* __restrict__ src =
            (const float4*)(Lf + (size_t)row * NB_ELEMS);
        #pragma unroll
        for (int it = 0; it < 17; ++it) {
            const int idx = it * 32 + lane;
            if (idx < NB_F4)
                asm volatile("cp.async.cg.shared.global [%0], [%1], 16;\n"
                             :: "r"(sbase0 + idx * 16), "l"(src + idx));
        }
    }
    asm volatile("cp.async.commit_group;\n");

    int buf = 0;
    for (; row < B; row += strd) {
        // ---- Prefetch next row into the other buffer (may be empty group) ----
        const int nrow = row + strd;
        if (nrow < B) {
            const float4* __restrict__ src =
                (const float4*)(Lf + (size_t)nrow * NB_ELEMS);
            const unsigned int d = buf ? sbase0 : sbase1;
            #pragma unroll
            for (int it = 0; it < 17; ++it) {
                const int idx = it * 32 + lane;
                if (idx < NB_F4)
                    asm volatile("cp.async.cg.shared.global [%0], [%1], 16;\n"
                                 :: "r"(d + idx * 16), "l"(src + idx));
            }
        }
        asm volatile("cp.async.commit_group;\n");

        // d-vector loads in flight before the wait
        const size_t vb = (size_t)row * NB_ACTIONS;
        const float a0 = a[vb + lane], m0 = mu[vb + lane];
        const float a1 = a[vb + j1],   m1 = mu[vb + j1];

        // ---- Current row's group (committed one row-period ago) ready ----
        asm volatile("cp.async.wait_group 1;\n" ::: "memory");
        __syncwarp();

        const float* __restrict__ sw = sbuf[wl][buf];
        const float dlo = a0 - m0;     // d[lane]
        const float dhi = a1 - m1;     // d[lane+32]

        const float diagRaw0 = sw[TRI(lane) + lane];
        const float diagRaw1 = sw[TRI(j1) + j1];

        float y0 = 0.0f;   // column j = lane
        float y1 = 0.0f;   // column j = lane + 32

        // Rows 0..31: y0 only; diagonal kept raw, corrected afterwards.
        #pragma unroll
        for (int i = 0; i < 32; ++i) {
            const float v  = sw[TRI(i) + lane];          // conflict-free LDS
            const float di = __shfl_sync(0xffffffffu, dlo, i);
            const float m  = (lane <= i) ? di : 0.0f;
            y0 = fmaf(v, m, y0);
        }

        // Rows 32..63: lo part always valid; hi part masked.
        #pragma unroll
        for (int i = 32; i < 64; ++i) {
            const int t = TRI(i);
            const float vlo = sw[t + lane];
            const float vhi = sw[t + j1];
            const float di  = __shfl_sync(0xffffffffu, dhi, i - 32);
            y0 = fmaf(vlo, di, y0);
            const float m = (j1 <= i) ? di : 0.0f;
            y1 = fmaf(vhi, m, y1);
        }

        // Diagonal correction: raw*d added in loops; want (exp(raw)+eps)*d.
        y0 = fmaf(expf(diagRaw0) + EPSV - diagRaw0, dlo, y0);
        y1 = fmaf(expf(diagRaw1) + EPSV - diagRaw1, dhi, y1);

        // quad = sum_j y_j^2 ; butterfly warp reduction
        float q = fmaf(y0, y0, y1 * y1);
        #pragma unroll
        for (int off = 16; off; off >>= 1)
            q += __shfl_xor_sync(0xffffffffu, q, off);

        if (lane == 0) out[row] = -0.5f * q;

        buf ^= 1;
    }
}

extern "C" void kernel_launch(void* const* d_in, const int* in_sizes, int n_in,
                              void* d_out, int out_size)
{
    const float* Lf = (const float*)d_in[0];   // [B, 2080]
    const float* mu = (const float*)d_in[1];   // [B, 64]
    const float* a  = (const float*)d_in[2];   // [B, 64]
    float* out = (float*)d_out;                // [B, 1]

    const int B = in_sizes[0] / NB_ELEMS;

    int blocks = (B + WPB - 1) / WPB;
    if (blocks > NBLOCKS) blocks = NBLOCKS;    // persistent grid

    naf_kernel<<<blocks, 32 * WPB>>>(Lf, mu, a, out, B);
}